// round 9
// baseline (speedup 1.0000x reference)
#include <cuda_runtime.h>
#include <cuda_fp16.h>
#include <cstdint>

// Problem dims
#define M_TOTAL 16384   // 8 * 2048
#define N_TOTAL 4096
#define K_TOTAL 4096

// GEMM tiling: 128x128 CTA tile, persistent CTAs, 2 per SM
#define BM 128
#define BN 128
#define BK 64
#define NK 64                    // K_TOTAL / BK iterations per tile
#define STAGES 3
#define THREADS 256              // 8 warps; 2x4 warp grid; warp tile 64x32

#define NUM_SMS 148
#define GRID (NUM_SMS * 2)       // 296 persistent CTAs
#define MT_TILES (M_TOTAL / BM)  // 128
#define NT_TILES (N_TOTAL / BN)  // 32
#define TOTAL_TILES (MT_TILES * NT_TILES)  // 4096

#define A_TILE_BYTES (BM * BK * 2)   // 16384
#define B_TILE_BYTES (BN * BK * 2)   // 16384
#define STAGE_BYTES (A_TILE_BYTES + B_TILE_BYTES)  // 32768
#define SMEM_MBAR   0                // full[3] @0+8s, free[3] @24+8s
#define SMEM_STAGE0 1024
#define SMEM_TOTAL  (SMEM_STAGE0 + STAGES * STAGE_BYTES)  // 99328 (x2 CTAs <= 227KB)

// fp16 operand buffers (device globals: no runtime allocation allowed)
__device__ __align__(1024) __half g_xh[(size_t)M_TOTAL * K_TOTAL];
__device__ __align__(1024) __half g_wh[(size_t)N_TOTAL * K_TOTAL];

// ---------------------------------------------------------------- helpers

__device__ __forceinline__ uint32_t smem_u32(const void* p) {
    uint32_t a;
    asm("{ .reg .u64 t; cvta.to.shared.u64 t, %1; cvt.u32.u64 %0, t; }" : "=r"(a) : "l"(p));
    return a;
}

__device__ __forceinline__ uint32_t swz128(uint32_t off) {
    return off ^ ((off >> 3) & 0x70);
}

__device__ __forceinline__ float quantize_ste(float w) {
    float a = fminf(fabsf(w), 1.0f);
    float q = rintf(a * 255.0f) * (1.0f / 255.0f);
    return copysignf(q, w);
}

__device__ __forceinline__ uint32_t h2_as_u32(__half2 h) {
    return *reinterpret_cast<uint32_t*>(&h);
}

__device__ __forceinline__ void cp_async16(uint32_t dst, const void* src) {
    asm volatile("cp.async.cg.shared.global [%0], [%1], 16;" :: "r"(dst), "l"(src) : "memory");
}
__device__ __forceinline__ void cp_async_arrive(uint32_t mbar) {
    asm volatile("cp.async.mbarrier.arrive.noinc.shared.b64 [%0];" :: "r"(mbar) : "memory");
}

#define MBAR_INIT(a, n) \
    asm volatile("mbarrier.init.shared.b64 [%0], %1;" :: "r"(a), "r"((uint32_t)(n)) : "memory")
#define MBAR_ARRIVE(a) \
    asm volatile("mbarrier.arrive.shared.b64 _, [%0];" :: "r"(a) : "memory")

__device__ __forceinline__ void mbar_wait(uint32_t mbar, uint32_t parity) {
    uint32_t done;
    asm volatile(
        "{\n\t.reg .pred p;\n\t"
        "mbarrier.try_wait.parity.acquire.cta.shared::cta.b64 p, [%1], %2;\n\t"
        "selp.b32 %0, 1, 0, p;\n\t}"
        : "=r"(done) : "r"(mbar), "r"(parity) : "memory");
    if (!done) {
        asm volatile(
            "{\n\t.reg .pred P1;\n\t"
            "WL_%=:\n\t"
            "mbarrier.try_wait.parity.acquire.cta.shared::cta.b64 P1, [%0], %1, 0x989680;\n\t"
            "@P1 bra.uni WD_%=;\n\t"
            "bra.uni WL_%=;\n\t"
            "WD_%=:\n\t}"
            :: "r"(mbar), "r"(parity) : "memory");
    }
}

__device__ __forceinline__ void ldsm_x4(uint32_t* r, uint32_t addr) {
    asm volatile("ldmatrix.sync.aligned.m8n8.x4.shared.b16 {%0,%1,%2,%3}, [%4];"
                 : "=r"(r[0]), "=r"(r[1]), "=r"(r[2]), "=r"(r[3]) : "r"(addr));
}

__device__ __forceinline__ void mma_16816(float* c, const uint32_t* a, uint32_t b0, uint32_t b1) {
    asm volatile(
        "mma.sync.aligned.m16n8k16.row.col.f32.f16.f16.f32 "
        "{%0,%1,%2,%3}, {%4,%5,%6,%7}, {%8,%9}, {%0,%1,%2,%3};"
        : "+f"(c[0]), "+f"(c[1]), "+f"(c[2]), "+f"(c[3])
        : "r"(a[0]), "r"(a[1]), "r"(a[2]), "r"(a[3]), "r"(b0), "r"(b1));
}

// ---------------------------------------------------------------- pre-pass kernels

__global__ void convert_x_kernel(const float* __restrict__ x) {
    size_t e = ((size_t)blockIdx.x * blockDim.x + threadIdx.x) * 8;
    float4 a = *reinterpret_cast<const float4*>(x + e);
    float4 b = *reinterpret_cast<const float4*>(x + e + 4);
    uint4 o;
    o.x = h2_as_u32(__floats2half2_rn(a.x, a.y));
    o.y = h2_as_u32(__floats2half2_rn(a.z, a.w));
    o.z = h2_as_u32(__floats2half2_rn(b.x, b.y));
    o.w = h2_as_u32(__floats2half2_rn(b.z, b.w));
    *reinterpret_cast<uint4*>(g_xh + e) = o;
}

__global__ void convert_w_kernel(const float* __restrict__ w) {
    size_t e = ((size_t)blockIdx.x * blockDim.x + threadIdx.x) * 8;
    float4 a = *reinterpret_cast<const float4*>(w + e);
    float4 b = *reinterpret_cast<const float4*>(w + e + 4);
    uint4 o;
    o.x = h2_as_u32(__floats2half2_rn(quantize_ste(a.x), quantize_ste(a.y)));
    o.y = h2_as_u32(__floats2half2_rn(quantize_ste(a.z), quantize_ste(a.w)));
    o.z = h2_as_u32(__floats2half2_rn(quantize_ste(b.x), quantize_ste(b.y)));
    o.w = h2_as_u32(__floats2half2_rn(quantize_ste(b.z), quantize_ste(b.w)));
    *reinterpret_cast<uint4*>(g_wh + e) = o;
}

// no-op: shifts launch index so ncu (-s 5 -c 1) lands on the GEMM
__global__ void align_nop_kernel() {}

// ---------------------------------------------------------------- GEMM kernel
// Persistent CTAs (296). Each walks tiles t = bid + i*296; the 3-stage mbarrier
// pipeline is indexed by a GLOBAL k-iteration count that never drains across
// tile boundaries: epilogue of tile i overlaps cp.async of tile i+1.

__global__ void __launch_bounds__(THREADS, 2)
bitlinear_gemm(const float* __restrict__ bias, float* __restrict__ out) {
    extern __shared__ char smem[];
    uint32_t sb = smem_u32(smem);
    const int tid = threadIdx.x;
    const int wid = tid >> 5, lane = tid & 31;
    const int warp_m = wid >> 2, warp_n = wid & 3;     // 2 x 4 warps
    const int bid = blockIdx.x;

    if (tid == 0) {
        #pragma unroll
        for (int s = 0; s < STAGES; s++) {
            MBAR_INIT(sb + SMEM_MBAR + s * 8, THREADS);       // full[s]
            MBAR_INIT(sb + SMEM_MBAR + 24 + s * 8, 8);        // free[s]
        }
    }
    __syncthreads();

    const int ntiles = (TOTAL_TILES - bid + GRID - 1) / GRID;  // 13 or 14
    const int G = ntiles * NK;                                  // global iterations

    // per-thread fixed copy coordinates
    const int arow = tid >> 1, akc0 = (tid & 1) * 4;   // A: rows 0..127, kc 0..7 (4 each)
    // B same shape

    // produce global iteration g: tile = g>>6, kt = g&63  -> stage g%3
    auto produce = [&](int g) {
        int t = bid + (g >> 6) * GRID;
        int kt = g & (NK - 1);
        int s = g % STAGES;
        const __half* asrc = g_xh + (size_t)(t >> 5) * BM * K_TOTAL + kt * BK;
        const __half* bsrc = g_wh + (size_t)(t & 31) * BN * K_TOTAL + kt * BK;
        uint32_t abase = sb + SMEM_STAGE0 + s * STAGE_BYTES;
        uint32_t bbase = abase + A_TILE_BYTES;
        #pragma unroll
        for (int i = 0; i < 4; i++) {
            int kc = akc0 + i;
            cp_async16(abase + swz128(arow * 128 + kc * 16),
                       asrc + (size_t)arow * K_TOTAL + kc * 8);
        }
        #pragma unroll
        for (int i = 0; i < 4; i++) {
            int kc = akc0 + i;
            cp_async16(bbase + swz128(arow * 128 + kc * 16),
                       bsrc + (size_t)arow * K_TOTAL + kc * 8);
        }
        cp_async_arrive(sb + SMEM_MBAR + s * 8);
    };

    produce(0);
    produce(1);

    // per-lane ldmatrix row mapping
    const int lrow = (lane & 7) + ((lane >> 3) & 1) * 8;
    const int lhi = lane >> 4;
    const int qrow = lane >> 2, qcol = (lane & 3) * 2;

    // pipeline cursors, continuous across tiles
    int cons_s = 0, cons_ph = 0;
    int prod_s = 2, prod_fw = 1;

    for (int tile = 0; tile < ntiles; tile++) {
        float acc[4][4][4];
        #pragma unroll
        for (int i = 0; i < 4; i++)
            #pragma unroll
            for (int j = 0; j < 4; j++)
                #pragma unroll
                for (int c = 0; c < 4; c++) acc[i][j][c] = 0.0f;

        for (int kt = 0; kt < NK; kt++) {
            int g = tile * NK + kt;
            // ---- produce stage for g+2 (may belong to next tile) ----
            if (g + 2 < G) {
                if (g > 0)
                    mbar_wait(sb + SMEM_MBAR + 24 + prod_s * 8, prod_fw);
                produce(g + 2);
                if (++prod_s == STAGES) { prod_s = 0; prod_fw ^= 1; }
            }

            // ---- consume stage g ----
            mbar_wait(sb + SMEM_MBAR + cons_s * 8, cons_ph);
            uint32_t abase = sb + SMEM_STAGE0 + cons_s * STAGE_BYTES;
            uint32_t bbase = abase + A_TILE_BYTES;

            #pragma unroll
            for (int kk = 0; kk < 4; kk++) {
                uint32_t a[4][4], b[2][4];
                #pragma unroll
                for (int mi = 0; mi < 4; mi++) {
                    int row = warp_m * 64 + mi * 16 + lrow;
                    ldsm_x4(a[mi], abase + swz128(row * 128 + (kk * 2 + lhi) * 16));
                }
                #pragma unroll
                for (int ni = 0; ni < 2; ni++) {
                    int row = warp_n * 32 + ni * 16 + lrow;
                    ldsm_x4(b[ni], bbase + swz128(row * 128 + (kk * 2 + lhi) * 16));
                }
                #pragma unroll
                for (int mi = 0; mi < 4; mi++)
                    #pragma unroll
                    for (int j = 0; j < 4; j++) {
                        int ni = j >> 1, sel = j & 1;
                        mma_16816(acc[mi][j], a[mi], b[ni][0 + sel], b[ni][2 + sel]);
                    }
            }

            if (lane == 0) MBAR_ARRIVE(sb + SMEM_MBAR + 24 + cons_s * 8);
            if (++cons_s == STAGES) { cons_s = 0; cons_ph ^= 1; }
        }

        // ---- epilogue for this tile (overlaps next tile's cp.async) ----
        int t = bid + tile * GRID;
        int mt = t >> 5, nt = t & 31;
        #pragma unroll
        for (int j = 0; j < 4; j++) {
            int n_off = warp_n * 32 + j * 8 + qcol;
            float b0 = quantize_ste(__ldg(bias + nt * BN + n_off));
            float b1 = quantize_ste(__ldg(bias + nt * BN + n_off + 1));
            #pragma unroll
            for (int mi = 0; mi < 4; mi++) {
                size_t m0 = (size_t)mt * BM + warp_m * 64 + mi * 16 + qrow;
                float* p0 = out + m0 * N_TOTAL + nt * BN + n_off;
                float* p1 = p0 + 8 * N_TOTAL;
                float2 v0 = {acc[mi][j][0] + b0, acc[mi][j][1] + b1};
                float2 v1 = {acc[mi][j][2] + b0, acc[mi][j][3] + b1};
                *reinterpret_cast<float2*>(p0) = v0;
                *reinterpret_cast<float2*>(p1) = v1;
            }
        }
    }
}

// ---------------------------------------------------------------- launch

extern "C" void kernel_launch(void* const* d_in, const int* in_sizes, int n_in,
                              void* d_out, int out_size) {
    const float* x = (const float*)d_in[0];       // [8, 2048, 4096]
    const float* w = (const float*)d_in[1];       // [4096, 4096]
    const float* b = (const float*)d_in[2];       // [4096]
    float* out = (float*)d_out;

    cudaFuncSetAttribute(bitlinear_gemm,
                         cudaFuncAttributeMaxDynamicSharedMemorySize, SMEM_TOTAL);

    convert_x_kernel<<<32768, 256>>>(x);          // 64M halfs / 8 per thread
    convert_w_kernel<<<8192, 256>>>(w);           // 16M halfs / 8 per thread
    align_nop_kernel<<<1, 32>>>();                // shift ncu -s 5 onto the GEMM
    bitlinear_gemm<<<GRID, THREADS, SMEM_TOTAL>>>(b, out);
}

// round 10
// speedup vs baseline: 1.3545x; 1.3545x over previous
#include <cuda_runtime.h>
#include <cuda_fp16.h>
#include <cstdint>

// Problem dims
#define M_TOTAL 16384   // 8 * 2048
#define N_TOTAL 4096
#define K_TOTAL 4096

// GEMM tiling: 128x128 CTA tile, persistent CTAs, 2 per SM
#define BM 128
#define BN 128
#define BK 64
#define NK 64                    // K_TOTAL / BK iterations per tile
#define STAGES 3
#define THREADS 256              // 8 warps; 2x4 warp grid; warp tile 64x32

#define NUM_SMS 148
#define GRID (NUM_SMS * 2)       // 296 persistent CTAs
#define MT_TILES (M_TOTAL / BM)  // 128
#define NT_TILES (N_TOTAL / BN)  // 32
#define TOTAL_TILES (MT_TILES * NT_TILES)  // 4096

#define A_TILE_BYTES (BM * BK * 2)   // 16384
#define B_TILE_BYTES (BN * BK * 2)   // 16384
#define STAGE_BYTES (A_TILE_BYTES + B_TILE_BYTES)  // 32768
#define SMEM_MBAR   0                // full[3] @0+8s, free[3] @24+8s
#define SMEM_STAGE0 1024
#define SMEM_TOTAL  (SMEM_STAGE0 + STAGES * STAGE_BYTES)  // 99328 (x2 CTAs <= 227KB)

// fp16 operand buffers (device globals: no runtime allocation allowed)
__device__ __align__(1024) __half g_xh[(size_t)M_TOTAL * K_TOTAL];
__device__ __align__(1024) __half g_wh[(size_t)N_TOTAL * K_TOTAL];

// ---------------------------------------------------------------- helpers

__device__ __forceinline__ uint32_t smem_u32(const void* p) {
    uint32_t a;
    asm("{ .reg .u64 t; cvta.to.shared.u64 t, %1; cvt.u32.u64 %0, t; }" : "=r"(a) : "l"(p));
    return a;
}

__device__ __forceinline__ uint32_t swz128(uint32_t off) {
    return off ^ ((off >> 3) & 0x70);
}

__device__ __forceinline__ float quantize_ste(float w) {
    float a = fminf(fabsf(w), 1.0f);
    float q = rintf(a * 255.0f) * (1.0f / 255.0f);
    return copysignf(q, w);
}

__device__ __forceinline__ uint32_t h2_as_u32(__half2 h) {
    return *reinterpret_cast<uint32_t*>(&h);
}

__device__ __forceinline__ void cp_async16(uint32_t dst, const void* src) {
    asm volatile("cp.async.cg.shared.global [%0], [%1], 16;" :: "r"(dst), "l"(src) : "memory");
}
__device__ __forceinline__ void cp_async_arrive(uint32_t mbar) {
    asm volatile("cp.async.mbarrier.arrive.noinc.shared.b64 [%0];" :: "r"(mbar) : "memory");
}

#define MBAR_INIT(a, n) \
    asm volatile("mbarrier.init.shared.b64 [%0], %1;" :: "r"(a), "r"((uint32_t)(n)) : "memory")
#define MBAR_ARRIVE(a) \
    asm volatile("mbarrier.arrive.shared.b64 _, [%0];" :: "r"(a) : "memory")

__device__ __forceinline__ void mbar_wait(uint32_t mbar, uint32_t parity) {
    uint32_t done;
    asm volatile(
        "{\n\t.reg .pred p;\n\t"
        "mbarrier.try_wait.parity.acquire.cta.shared::cta.b64 p, [%1], %2;\n\t"
        "selp.b32 %0, 1, 0, p;\n\t}"
        : "=r"(done) : "r"(mbar), "r"(parity) : "memory");
    if (!done) {
        asm volatile(
            "{\n\t.reg .pred P1;\n\t"
            "WL_%=:\n\t"
            "mbarrier.try_wait.parity.acquire.cta.shared::cta.b64 P1, [%0], %1, 0x989680;\n\t"
            "@P1 bra.uni WD_%=;\n\t"
            "bra.uni WL_%=;\n\t"
            "WD_%=:\n\t}"
            :: "r"(mbar), "r"(parity) : "memory");
    }
}

__device__ __forceinline__ void ldsm_x4(uint32_t* r, uint32_t addr) {
    asm volatile("ldmatrix.sync.aligned.m8n8.x4.shared.b16 {%0,%1,%2,%3}, [%4];"
                 : "=r"(r[0]), "=r"(r[1]), "=r"(r[2]), "=r"(r[3]) : "r"(addr));
}

__device__ __forceinline__ void mma_16816(float* c, const uint32_t* a, uint32_t b0, uint32_t b1) {
    asm volatile(
        "mma.sync.aligned.m16n8k16.row.col.f32.f16.f16.f32 "
        "{%0,%1,%2,%3}, {%4,%5,%6,%7}, {%8,%9}, {%0,%1,%2,%3};"
        : "+f"(c[0]), "+f"(c[1]), "+f"(c[2]), "+f"(c[3])
        : "r"(a[0]), "r"(a[1]), "r"(a[2]), "r"(a[3]), "r"(b0), "r"(b1));
}

// ---------------------------------------------------------------- pre-pass kernels

__global__ void convert_x_kernel(const float* __restrict__ x) {
    size_t e = ((size_t)blockIdx.x * blockDim.x + threadIdx.x) * 8;
    float4 a = *reinterpret_cast<const float4*>(x + e);
    float4 b = *reinterpret_cast<const float4*>(x + e + 4);
    uint4 o;
    o.x = h2_as_u32(__floats2half2_rn(a.x, a.y));
    o.y = h2_as_u32(__floats2half2_rn(a.z, a.w));
    o.z = h2_as_u32(__floats2half2_rn(b.x, b.y));
    o.w = h2_as_u32(__floats2half2_rn(b.z, b.w));
    *reinterpret_cast<uint4*>(g_xh + e) = o;
}

__global__ void convert_w_kernel(const float* __restrict__ w) {
    size_t e = ((size_t)blockIdx.x * blockDim.x + threadIdx.x) * 8;
    float4 a = *reinterpret_cast<const float4*>(w + e);
    float4 b = *reinterpret_cast<const float4*>(w + e + 4);
    uint4 o;
    o.x = h2_as_u32(__floats2half2_rn(quantize_ste(a.x), quantize_ste(a.y)));
    o.y = h2_as_u32(__floats2half2_rn(quantize_ste(a.z), quantize_ste(a.w)));
    o.z = h2_as_u32(__floats2half2_rn(quantize_ste(b.x), quantize_ste(b.y)));
    o.w = h2_as_u32(__floats2half2_rn(quantize_ste(b.z), quantize_ste(b.w)));
    *reinterpret_cast<uint4*>(g_wh + e) = o;
}

// no-op: shifts launch index so ncu (-s 5 -c 1) lands on the GEMM
__global__ void align_nop_kernel() {}

// ---------------------------------------------------------------- GEMM kernel
// Persistent CTAs (296), continuous 3-stage pipeline across tile boundaries.
// Copy mapping = R6's warp-coalesced form (consecutive lanes -> consecutive
// 16B chunks) so cp.async requests merge into full sectors at L2.

__global__ void __launch_bounds__(THREADS, 2)
bitlinear_gemm(const float* __restrict__ bias, float* __restrict__ out) {
    extern __shared__ char smem[];
    uint32_t sb = smem_u32(smem);
    const int tid = threadIdx.x;
    const int wid = tid >> 5, lane = tid & 31;
    const int warp_m = wid >> 2, warp_n = wid & 3;     // 2 x 4 warps
    const int bid = blockIdx.x;

    if (tid == 0) {
        #pragma unroll
        for (int s = 0; s < STAGES; s++) {
            MBAR_INIT(sb + SMEM_MBAR + s * 8, THREADS);       // full[s]
            MBAR_INIT(sb + SMEM_MBAR + 24 + s * 8, 8);        // free[s]
        }
    }
    __syncthreads();

    const int ntiles = (TOTAL_TILES - bid + GRID - 1) / GRID;  // 13 or 14
    const int G = ntiles * NK;                                  // global iterations

    // produce global iteration g: tile = g>>6, kt = g&63  -> stage g%3
    // R6 coalesced mapping: c = tid + i*THREADS, row = c>>3, kc = c&7
    auto produce = [&](int g) {
        int t = bid + (g >> 6) * GRID;
        int kt = g & (NK - 1);
        int s = g % STAGES;
        const __half* asrc = g_xh + (size_t)(t >> 5) * BM * K_TOTAL + kt * BK;
        const __half* bsrc = g_wh + (size_t)(t & 31) * BN * K_TOTAL + kt * BK;
        uint32_t abase = sb + SMEM_STAGE0 + s * STAGE_BYTES;
        uint32_t bbase = abase + A_TILE_BYTES;
        #pragma unroll
        for (int i = 0; i < 4; i++) {
            int c = tid + i * THREADS;            // 0..1023
            int row = c >> 3, kc = c & 7;
            cp_async16(abase + swz128(row * 128 + kc * 16),
                       asrc + (size_t)row * K_TOTAL + kc * 8);
        }
        #pragma unroll
        for (int i = 0; i < 4; i++) {
            int c = tid + i * THREADS;
            int row = c >> 3, kc = c & 7;
            cp_async16(bbase + swz128(row * 128 + kc * 16),
                       bsrc + (size_t)row * K_TOTAL + kc * 8);
        }
        cp_async_arrive(sb + SMEM_MBAR + s * 8);
    };

    produce(0);
    produce(1);

    // per-lane ldmatrix row mapping
    const int lrow = (lane & 7) + ((lane >> 3) & 1) * 8;
    const int lhi = lane >> 4;
    const int qrow = lane >> 2, qcol = (lane & 3) * 2;

    // pipeline cursors, continuous across tiles
    int cons_s = 0, cons_ph = 0;
    int prod_s = 2, prod_fw = 1;

    for (int tile = 0; tile < ntiles; tile++) {
        float acc[4][4][4];
        #pragma unroll
        for (int i = 0; i < 4; i++)
            #pragma unroll
            for (int j = 0; j < 4; j++)
                #pragma unroll
                for (int c = 0; c < 4; c++) acc[i][j][c] = 0.0f;

        for (int kt = 0; kt < NK; kt++) {
            int g = tile * NK + kt;
            // ---- produce stage for g+2 (may belong to next tile) ----
            if (g + 2 < G) {
                if (g > 0)
                    mbar_wait(sb + SMEM_MBAR + 24 + prod_s * 8, prod_fw);
                produce(g + 2);
                if (++prod_s == STAGES) { prod_s = 0; prod_fw ^= 1; }
            }

            // ---- consume stage g ----
            mbar_wait(sb + SMEM_MBAR + cons_s * 8, cons_ph);
            uint32_t abase = sb + SMEM_STAGE0 + cons_s * STAGE_BYTES;
            uint32_t bbase = abase + A_TILE_BYTES;

            #pragma unroll
            for (int kk = 0; kk < 4; kk++) {
                uint32_t a[4][4], b[2][4];
                #pragma unroll
                for (int mi = 0; mi < 4; mi++) {
                    int row = warp_m * 64 + mi * 16 + lrow;
                    ldsm_x4(a[mi], abase + swz128(row * 128 + (kk * 2 + lhi) * 16));
                }
                #pragma unroll
                for (int ni = 0; ni < 2; ni++) {
                    int row = warp_n * 32 + ni * 16 + lrow;
                    ldsm_x4(b[ni], bbase + swz128(row * 128 + (kk * 2 + lhi) * 16));
                }
                #pragma unroll
                for (int mi = 0; mi < 4; mi++)
                    #pragma unroll
                    for (int j = 0; j < 4; j++) {
                        int ni = j >> 1, sel = j & 1;
                        mma_16816(acc[mi][j], a[mi], b[ni][0 + sel], b[ni][2 + sel]);
                    }
            }

            if (lane == 0) MBAR_ARRIVE(sb + SMEM_MBAR + 24 + cons_s * 8);
            if (++cons_s == STAGES) { cons_s = 0; cons_ph ^= 1; }
        }

        // ---- epilogue for this tile (overlaps next tile's cp.async) ----
        int t = bid + tile * GRID;
        int mt = t >> 5, nt = t & 31;
        #pragma unroll
        for (int j = 0; j < 4; j++) {
            int n_off = warp_n * 32 + j * 8 + qcol;
            float b0 = quantize_ste(__ldg(bias + nt * BN + n_off));
            float b1 = quantize_ste(__ldg(bias + nt * BN + n_off + 1));
            #pragma unroll
            for (int mi = 0; mi < 4; mi++) {
                size_t m0 = (size_t)mt * BM + warp_m * 64 + mi * 16 + qrow;
                float* p0 = out + m0 * N_TOTAL + nt * BN + n_off;
                float* p1 = p0 + 8 * N_TOTAL;
                float2 v0 = {acc[mi][j][0] + b0, acc[mi][j][1] + b1};
                float2 v1 = {acc[mi][j][2] + b0, acc[mi][j][3] + b1};
                *reinterpret_cast<float2*>(p0) = v0;
                *reinterpret_cast<float2*>(p1) = v1;
            }
        }
    }
}

// ---------------------------------------------------------------- launch

extern "C" void kernel_launch(void* const* d_in, const int* in_sizes, int n_in,
                              void* d_out, int out_size) {
    const float* x = (const float*)d_in[0];       // [8, 2048, 4096]
    const float* w = (const float*)d_in[1];       // [4096, 4096]
    const float* b = (const float*)d_in[2];       // [4096]
    float* out = (float*)d_out;

    cudaFuncSetAttribute(bitlinear_gemm,
                         cudaFuncAttributeMaxDynamicSharedMemorySize, SMEM_TOTAL);

    convert_x_kernel<<<32768, 256>>>(x);          // 64M halfs / 8 per thread
    convert_w_kernel<<<8192, 256>>>(w);           // 16M halfs / 8 per thread
    align_nop_kernel<<<1, 32>>>();                // shift ncu -s 5 onto the GEMM
    bitlinear_gemm<<<GRID, THREADS, SMEM_TOTAL>>>(b, out);
}

// round 12
// speedup vs baseline: 1.4724x; 1.0870x over previous
#include <cuda_runtime.h>
#include <cuda_fp16.h>
#include <cstdint>

// Problem dims
#define M_TOTAL 16384   // 8 * 2048
#define N_TOTAL 4096
#define K_TOTAL 4096

// GEMM tiling: 128x128 CTA tile, 2 CTAs resident per SM
#define BM 128
#define BN 128
#define BK 64
#define NK (K_TOTAL / BK)        // 64 mainloop iterations
#define STAGES 3
#define THREADS 256              // 8 warps; 2x4 warp grid; warp tile 64x32

#define A_TILE_BYTES (BM * BK * 2)   // 16384
#define B_TILE_BYTES (BN * BK * 2)   // 16384
#define STAGE_BYTES (A_TILE_BYTES + B_TILE_BYTES)  // 32768
#define SMEM_BIAS   0                // 128 floats
#define SMEM_MBAR   512              // full[3] @512+8s, free[3] @536+8s
#define SMEM_STAGE0 1024
#define SMEM_TOTAL  (SMEM_STAGE0 + STAGES * STAGE_BYTES)  // 99328 (x2 CTAs <= 227KB)

// fp16 operand buffers (device globals: no runtime allocation allowed)
__device__ __align__(1024) __half g_xh[(size_t)M_TOTAL * K_TOTAL];
__device__ __align__(1024) __half g_wh[(size_t)N_TOTAL * K_TOTAL];

// ---------------------------------------------------------------- helpers

__device__ __forceinline__ uint32_t smem_u32(const void* p) {
    uint32_t a;
    asm("{ .reg .u64 t; cvta.to.shared.u64 t, %1; cvt.u32.u64 %0, t; }" : "=r"(a) : "l"(p));
    return a;
}

__device__ __forceinline__ uint32_t swz128(uint32_t off) {
    return off ^ ((off >> 3) & 0x70);
}

__device__ __forceinline__ float quantize_ste(float w) {
    float a = fminf(fabsf(w), 1.0f);
    float q = rintf(a * 255.0f) * (1.0f / 255.0f);
    return copysignf(q, w);
}

__device__ __forceinline__ uint32_t h2_as_u32(__half2 h) {
    return *reinterpret_cast<uint32_t*>(&h);
}

__device__ __forceinline__ void cp_async16(uint32_t dst, const void* src) {
    asm volatile("cp.async.cg.shared.global [%0], [%1], 16;" :: "r"(dst), "l"(src) : "memory");
}
__device__ __forceinline__ void cp_async_arrive(uint32_t mbar) {
    asm volatile("cp.async.mbarrier.arrive.noinc.shared.b64 [%0];" :: "r"(mbar) : "memory");
}

#define MBAR_INIT(a, n) \
    asm volatile("mbarrier.init.shared.b64 [%0], %1;" :: "r"(a), "r"((uint32_t)(n)) : "memory")
#define MBAR_ARRIVE(a) \
    asm volatile("mbarrier.arrive.shared.b64 _, [%0];" :: "r"(a) : "memory")

__device__ __forceinline__ void mbar_wait(uint32_t mbar, uint32_t parity) {
    uint32_t done;
    asm volatile(
        "{\n\t.reg .pred p;\n\t"
        "mbarrier.try_wait.parity.acquire.cta.shared::cta.b64 p, [%1], %2;\n\t"
        "selp.b32 %0, 1, 0, p;\n\t}"
        : "=r"(done) : "r"(mbar), "r"(parity) : "memory");
    if (!done) {
        asm volatile(
            "{\n\t.reg .pred P1;\n\t"
            "WL_%=:\n\t"
            "mbarrier.try_wait.parity.acquire.cta.shared::cta.b64 P1, [%0], %1, 0x989680;\n\t"
            "@P1 bra.uni WD_%=;\n\t"
            "bra.uni WL_%=;\n\t"
            "WD_%=:\n\t}"
            :: "r"(mbar), "r"(parity) : "memory");
    }
}

__device__ __forceinline__ void ldsm_x4(uint32_t* r, uint32_t addr) {
    asm volatile("ldmatrix.sync.aligned.m8n8.x4.shared.b16 {%0,%1,%2,%3}, [%4];"
                 : "=r"(r[0]), "=r"(r[1]), "=r"(r[2]), "=r"(r[3]) : "r"(addr));
}

__device__ __forceinline__ void mma_16816(float* c, const uint32_t* a, uint32_t b0, uint32_t b1) {
    asm volatile(
        "mma.sync.aligned.m16n8k16.row.col.f32.f16.f16.f32 "
        "{%0,%1,%2,%3}, {%4,%5,%6,%7}, {%8,%9}, {%0,%1,%2,%3};"
        : "+f"(c[0]), "+f"(c[1]), "+f"(c[2]), "+f"(c[3])
        : "r"(a[0]), "r"(a[1]), "r"(a[2]), "r"(a[3]), "r"(b0), "r"(b1));
}

// ---------------------------------------------------------------- pre-pass kernels

__global__ void convert_x_kernel(const float* __restrict__ x) {
    size_t e = ((size_t)blockIdx.x * blockDim.x + threadIdx.x) * 8;
    float4 a = *reinterpret_cast<const float4*>(x + e);
    float4 b = *reinterpret_cast<const float4*>(x + e + 4);
    uint4 o;
    o.x = h2_as_u32(__floats2half2_rn(a.x, a.y));
    o.y = h2_as_u32(__floats2half2_rn(a.z, a.w));
    o.z = h2_as_u32(__floats2half2_rn(b.x, b.y));
    o.w = h2_as_u32(__floats2half2_rn(b.z, b.w));
    *reinterpret_cast<uint4*>(g_xh + e) = o;
}

__global__ void convert_w_kernel(const float* __restrict__ w) {
    size_t e = ((size_t)blockIdx.x * blockDim.x + threadIdx.x) * 8;
    float4 a = *reinterpret_cast<const float4*>(w + e);
    float4 b = *reinterpret_cast<const float4*>(w + e + 4);
    uint4 o;
    o.x = h2_as_u32(__floats2half2_rn(quantize_ste(a.x), quantize_ste(a.y)));
    o.y = h2_as_u32(__floats2half2_rn(quantize_ste(a.z), quantize_ste(a.w)));
    o.z = h2_as_u32(__floats2half2_rn(quantize_ste(b.x), quantize_ste(b.y)));
    o.w = h2_as_u32(__floats2half2_rn(quantize_ste(b.z), quantize_ste(b.w)));
    *reinterpret_cast<uint4*>(g_wh + e) = o;
}

// no-op: shifts launch index so ncu (-s 5 -c 1) lands on the GEMM
__global__ void align_nop_kernel() {}

// ---------------------------------------------------------------- GEMM kernel
// CTA 128x128, BK=64, 256 threads, 8 warps (2 x 4), warp tile 64x32, 2 CTAs/SM.
// Per-stage mbarrier pipeline; strength-reduced producer (pointer bumps only);
// early stage release after the last ldmatrix of each iteration.
//
// Parity bookkeeping (the R11 deadlock): free-waits hit stages in order
// 0,1,2,0,1,2,... starting at kt=1. The FIRST wait on each stage must use
// parity 0 (first phase completion), so prod_fw starts at 0 and flips after
// the wait on stage STAGES-1.

__global__ void __launch_bounds__(THREADS, 2)
bitlinear_gemm(const float* __restrict__ bias, float* __restrict__ out) {
    extern __shared__ char smem[];
    uint32_t sb = smem_u32(smem);
    const int tid = threadIdx.x;
    const int wid = tid >> 5, lane = tid & 31;
    const int warp_m = wid >> 2, warp_n = wid & 3;     // 2 x 4 warps
    const uint32_t mt = blockIdx.y, nt = blockIdx.x;

    float* qb = reinterpret_cast<float*>(smem + SMEM_BIAS);
    if (tid < BN) qb[tid] = quantize_ste(bias[nt * BN + tid]);

    if (tid == 0) {
        #pragma unroll
        for (int s = 0; s < STAGES; s++) {
            MBAR_INIT(sb + SMEM_MBAR + s * 8, THREADS);       // full[s]
            MBAR_INIT(sb + SMEM_MBAR + 24 + s * 8, 8);        // free[s]
        }
    }
    __syncthreads();

    // ---- strength-reduced producer state ----
    // thread's chunk i (i<4): c = tid + i*256 -> row = (tid>>3) + i*32, kc = tid&7
    // gmem offset(i) = offset(0) + i*32*K_TOTAL halfs; smem offset(i) = swz(off0) + i*4096
    // (swz128 only permutes bits [6:4]; +4096 leaves bits [0:9] unchanged)
    const int trow = tid >> 3, tkc = tid & 7;
    const __half* aptr = g_xh + (size_t)mt * BM * K_TOTAL + (size_t)trow * K_TOTAL + tkc * 8;
    const __half* bptr = g_wh + (size_t)nt * BN * K_TOTAL + (size_t)trow * K_TOTAL + tkc * 8;
    const uint32_t adst0 = sb + SMEM_STAGE0 + swz128(trow * 128 + tkc * 16);
    const uint32_t bdst0 = adst0 + A_TILE_BYTES;

    int psd = 0;   // producer stage cursor (sequential produce calls)
    auto produce = [&]() {
        uint32_t as = adst0 + psd * STAGE_BYTES;
        uint32_t bs = bdst0 + psd * STAGE_BYTES;
        #pragma unroll
        for (int i = 0; i < 4; i++)
            cp_async16(as + i * 4096, aptr + (size_t)i * 32 * K_TOTAL);
        #pragma unroll
        for (int i = 0; i < 4; i++)
            cp_async16(bs + i * 4096, bptr + (size_t)i * 32 * K_TOTAL);
        cp_async_arrive(sb + SMEM_MBAR + psd * 8);
        aptr += BK;
        bptr += BK;
        if (++psd == STAGES) psd = 0;
    };

    produce();   // kt = 0 -> stage 0
    produce();   // kt = 1 -> stage 1

    // per-lane ldmatrix row mapping
    const int lrow = (lane & 7) + ((lane >> 3) & 1) * 8;
    const int lhi = lane >> 4;

    float acc[4][4][4];
    #pragma unroll
    for (int i = 0; i < 4; i++)
        #pragma unroll
        for (int j = 0; j < 4; j++)
            #pragma unroll
            for (int c = 0; c < 4; c++) acc[i][j][c] = 0.0f;

    // pipeline cursors
    int cons_s = 0, cons_ph = 0;                 // consumer: stage, full-parity
    int prod_fw = 0;                             // producer free-wait parity (FIX: starts 0)

    for (int kt = 0; kt < NK; kt++) {
        // ---- produce stage for kt+2 ----
        if (kt + 2 < NK) {
            if (kt > 0) {
                mbar_wait(sb + SMEM_MBAR + 24 + psd * 8, prod_fw);
                if (psd == STAGES - 1) prod_fw ^= 1;   // next cycle of stages uses flipped parity
            }
            produce();
        }

        // ---- consume stage kt ----
        mbar_wait(sb + SMEM_MBAR + cons_s * 8, cons_ph);
        uint32_t abase = sb + SMEM_STAGE0 + cons_s * STAGE_BYTES;
        uint32_t bbase = abase + A_TILE_BYTES;

        #pragma unroll
        for (int kk = 0; kk < 4; kk++) {          // 4 k16-steps per BK=64
            uint32_t a[4][4], b[2][4];
            #pragma unroll
            for (int mi = 0; mi < 4; mi++) {
                int row = warp_m * 64 + mi * 16 + lrow;
                ldsm_x4(a[mi], abase + swz128(row * 128 + (kk * 2 + lhi) * 16));
            }
            #pragma unroll
            for (int ni = 0; ni < 2; ni++) {
                int row = warp_n * 32 + ni * 16 + lrow;
                ldsm_x4(b[ni], bbase + swz128(row * 128 + (kk * 2 + lhi) * 16));
            }
            // early release: after the LAST ldmatrix of this stage, before final MMAs
            if (kk == 3 && lane == 0) MBAR_ARRIVE(sb + SMEM_MBAR + 24 + cons_s * 8);
            #pragma unroll
            for (int mi = 0; mi < 4; mi++)
                #pragma unroll
                for (int j = 0; j < 4; j++) {
                    int ni = j >> 1, sel = j & 1;
                    mma_16816(acc[mi][j], a[mi], b[ni][0 + sel], b[ni][2 + sel]);
                }
        }

        if (++cons_s == STAGES) { cons_s = 0; cons_ph ^= 1; }
    }

    // ---- epilogue: registers -> gmem with quantized bias (qb visible since init sync) ----
    const int qrow = lane >> 2, qcol = (lane & 3) * 2;
    #pragma unroll
    for (int mi = 0; mi < 4; mi++) {
        #pragma unroll
        for (int j = 0; j < 4; j++) {
            int n_off = warp_n * 32 + j * 8 + qcol;
            float b0 = qb[n_off], b1 = qb[n_off + 1];
            size_t m0 = (size_t)mt * BM + warp_m * 64 + mi * 16 + qrow;
            float* p0 = out + m0 * N_TOTAL + nt * BN + n_off;
            float* p1 = p0 + 8 * N_TOTAL;
            float2 v0 = {acc[mi][j][0] + b0, acc[mi][j][1] + b1};
            float2 v1 = {acc[mi][j][2] + b0, acc[mi][j][3] + b1};
            *reinterpret_cast<float2*>(p0) = v0;
            *reinterpret_cast<float2*>(p1) = v1;
        }
    }
}

// ---------------------------------------------------------------- launch

extern "C" void kernel_launch(void* const* d_in, const int* in_sizes, int n_in,
                              void* d_out, int out_size) {
    const float* x = (const float*)d_in[0];       // [8, 2048, 4096]
    const float* w = (const float*)d_in[1];       // [4096, 4096]
    const float* b = (const float*)d_in[2];       // [4096]
    float* out = (float*)d_out;

    cudaFuncSetAttribute(bitlinear_gemm,
                         cudaFuncAttributeMaxDynamicSharedMemorySize, SMEM_TOTAL);

    convert_x_kernel<<<32768, 256>>>(x);          // 64M halfs / 8 per thread
    convert_w_kernel<<<8192, 256>>>(w);           // 16M halfs / 8 per thread
    align_nop_kernel<<<1, 32>>>();                // shift ncu -s 5 onto the GEMM
    bitlinear_gemm<<<dim3(N_TOTAL / BN, M_TOTAL / BM), THREADS, SMEM_TOTAL>>>(b, out);
}